// round 4
// baseline (speedup 1.0000x reference)
#include <cuda_runtime.h>

#define NJ 24

// Ancestor chains (root -> joint) for the fixed SMPL tree.
__device__ const int d_chain[NJ][9] = {
    {0,0,0,0,0,0,0,0,0},
    {0,1,0,0,0,0,0,0,0},
    {0,2,0,0,0,0,0,0,0},
    {0,3,0,0,0,0,0,0,0},
    {0,1,4,0,0,0,0,0,0},
    {0,2,5,0,0,0,0,0,0},
    {0,3,6,0,0,0,0,0,0},
    {0,1,4,7,0,0,0,0,0},
    {0,2,5,8,0,0,0,0,0},
    {0,3,6,9,0,0,0,0,0},
    {0,1,4,7,10,0,0,0,0},
    {0,2,5,8,11,0,0,0,0},
    {0,3,6,9,12,0,0,0,0},
    {0,3,6,9,13,0,0,0,0},
    {0,3,6,9,14,0,0,0,0},
    {0,3,6,9,12,15,0,0,0},
    {0,3,6,9,13,16,0,0,0},
    {0,3,6,9,14,17,0,0,0},
    {0,3,6,9,13,16,18,0,0},
    {0,3,6,9,14,17,19,0,0},
    {0,3,6,9,13,16,18,20,0},
    {0,3,6,9,14,17,19,21,0},
    {0,3,6,9,13,16,18,20,22},
    {0,3,6,9,14,17,19,21,23},
};
__device__ const int d_chlen[NJ] = {1,2,2,2,3,3,3,4,4,4,5,5,5,5,5,6,6,6,7,7,8,8,9,9};

typedef unsigned long long u64;

__device__ __forceinline__ u64 fma2(u64 a, u64 b, u64 c) {
    u64 d;
    asm("fma.rn.f32x2 %0, %1, %2, %3;" : "=l"(d) : "l"(a), "l"(b), "l"(c));
    return d;
}
__device__ __forceinline__ u64 mul2(u64 a, u64 b) {
    u64 d;
    asm("mul.rn.f32x2 %0, %1, %2;" : "=l"(d) : "l"(a), "l"(b));
    return d;
}
__device__ __forceinline__ u64 pack2(float f) {
    unsigned int u = __float_as_uint(f);
    return ((u64)u << 32) | (u64)u;
}

__global__ __launch_bounds__(256, 4)
void skin_kernel(const float* __restrict__ normals,
                 const float* __restrict__ pose,
                 const float* __restrict__ W,
                 float* __restrict__ out,
                 int N)
{
    __shared__ float sLoc[NJ][9];      // local per-joint rotations
    __shared__ u64   sRp[NJ][9];       // composed rotations, each element duplicated as f32x2
    __shared__ float sRs[NJ][9];       // scalar copy (tail path)

    const int b = blockIdx.y;
    const int tid = threadIdx.x;

    // --- Rodrigues (one thread per joint) ---
    if (tid < NJ) {
        const float x = pose[b * 72 + tid * 3 + 0];
        const float y = pose[b * 72 + tid * 3 + 1];
        const float z = pose[b * 72 + tid * 3 + 2];
        const float e = 1e-8f;
        const float a = sqrtf((x + e) * (x + e) + (y + e) * (y + e) + (z + e) * (z + e));
        const float inv = 1.0f / a;
        const float ux = x * inv, uy = y * inv, uz = z * inv;
        float s, c;
        sincosf(a, &s, &c);
        const float C = 1.0f - c;
        sLoc[tid][0] = c + C * ux * ux;
        sLoc[tid][1] = C * ux * uy - s * uz;
        sLoc[tid][2] = C * ux * uz + s * uy;
        sLoc[tid][3] = C * uy * ux + s * uz;
        sLoc[tid][4] = c + C * uy * uy;
        sLoc[tid][5] = C * uy * uz - s * ux;
        sLoc[tid][6] = C * uz * ux - s * uy;
        sLoc[tid][7] = C * uz * uy + s * ux;
        sLoc[tid][8] = c + C * uz * uz;
    }
    __syncthreads();

    // --- parallel chain composition: each joint-thread walks its own ancestor path ---
    if (tid < NJ) {
        float R[9];
        #pragma unroll
        for (int e2 = 0; e2 < 9; e2++) R[e2] = sLoc[0][e2];
        const int len = d_chlen[tid];
        for (int i = 1; i < len; i++) {
            const int j = d_chain[tid][i];
            float T[9];
            #pragma unroll
            for (int r = 0; r < 3; r++)
                #pragma unroll
                for (int cc = 0; cc < 3; cc++)
                    T[r * 3 + cc] = R[r * 3 + 0] * sLoc[j][0 * 3 + cc]
                                  + R[r * 3 + 1] * sLoc[j][1 * 3 + cc]
                                  + R[r * 3 + 2] * sLoc[j][2 * 3 + cc];
            #pragma unroll
            for (int e2 = 0; e2 < 9; e2++) R[e2] = T[e2];
        }
        #pragma unroll
        for (int e2 = 0; e2 < 9; e2++) {
            sRs[tid][e2] = R[e2];
            sRp[tid][e2] = pack2(R[e2]);
        }
    }
    __syncthreads();

    const float* Nb = normals + (size_t)b * 3 * N;
    const float* Wb = W + (size_t)b * NJ * N;
    float* Ob = out + (size_t)b * 3 * N;

    const int G = N >> 2;                       // full groups of 4 points
    const int stride = gridDim.x * blockDim.x;

    for (int g = blockIdx.x * blockDim.x + tid; g < G; g += stride) {
        const int n = g << 2;

        const ulonglong2 nx = *reinterpret_cast<const ulonglong2*>(Nb + n);
        const ulonglong2 ny = *reinterpret_cast<const ulonglong2*>(Nb + (size_t)N + n);
        const ulonglong2 nz = *reinterpret_cast<const ulonglong2*>(Nb + 2 * (size_t)N + n);

        u64 a00 = 0, a01 = 0, a10 = 0, a11 = 0, a20 = 0, a21 = 0;

        #pragma unroll
        for (int kb = 0; kb < 6; kb++) {
            // burst of 4 weight loads -> MLP
            ulonglong2 w[4];
            #pragma unroll
            for (int t = 0; t < 4; t++)
                w[t] = *reinterpret_cast<const ulonglong2*>(Wb + (size_t)(kb * 4 + t) * N + n);

            #pragma unroll
            for (int t = 0; t < 4; t++) {
                const int k = kb * 4 + t;
                u64 v;
                // row 0
                {
                    const u64 r0 = sRp[k][0], r1 = sRp[k][1], r2 = sRp[k][2];
                    v = mul2(r0, nx.x); v = fma2(r1, ny.x, v); v = fma2(r2, nz.x, v);
                    a00 = fma2(w[t].x, v, a00);
                    v = mul2(r0, nx.y); v = fma2(r1, ny.y, v); v = fma2(r2, nz.y, v);
                    a01 = fma2(w[t].y, v, a01);
                }
                // row 1
                {
                    const u64 r3 = sRp[k][3], r4 = sRp[k][4], r5 = sRp[k][5];
                    v = mul2(r3, nx.x); v = fma2(r4, ny.x, v); v = fma2(r5, nz.x, v);
                    a10 = fma2(w[t].x, v, a10);
                    v = mul2(r3, nx.y); v = fma2(r4, ny.y, v); v = fma2(r5, nz.y, v);
                    a11 = fma2(w[t].y, v, a11);
                }
                // row 2
                {
                    const u64 r6 = sRp[k][6], r7 = sRp[k][7], r8 = sRp[k][8];
                    v = mul2(r6, nx.x); v = fma2(r7, ny.x, v); v = fma2(r8, nz.x, v);
                    a20 = fma2(w[t].x, v, a20);
                    v = mul2(r6, nx.y); v = fma2(r7, ny.y, v); v = fma2(r8, nz.y, v);
                    a21 = fma2(w[t].y, v, a21);
                }
            }
        }

        ulonglong2 o;
        o.x = a00; o.y = a01;
        *reinterpret_cast<ulonglong2*>(Ob + n) = o;
        o.x = a10; o.y = a11;
        *reinterpret_cast<ulonglong2*>(Ob + (size_t)N + n) = o;
        o.x = a20; o.y = a21;
        *reinterpret_cast<ulonglong2*>(Ob + 2 * (size_t)N + n) = o;
    }

    // --- scalar tail (N % 4 leftover points) ---
    const int rem = N & 3;
    if (rem && blockIdx.x == 0 && tid < rem) {
        const int n = (G << 2) + tid;
        const float xs = Nb[n], ys = Nb[(size_t)N + n], zs = Nb[2 * (size_t)N + n];
        float o0 = 0.f, o1 = 0.f, o2 = 0.f;
        for (int k = 0; k < NJ; k++) {
            const float wv = Wb[(size_t)k * N + n];
            o0 = fmaf(wv, sRs[k][0] * xs + sRs[k][1] * ys + sRs[k][2] * zs, o0);
            o1 = fmaf(wv, sRs[k][3] * xs + sRs[k][4] * ys + sRs[k][5] * zs, o1);
            o2 = fmaf(wv, sRs[k][6] * xs + sRs[k][7] * ys + sRs[k][8] * zs, o2);
        }
        Ob[n] = o0;
        Ob[(size_t)N + n] = o1;
        Ob[2 * (size_t)N + n] = o2;
    }
}

extern "C" void kernel_launch(void* const* d_in, const int* in_sizes, int n_in,
                              void* d_out, int out_size)
{
    const float* normals = (const float*)d_in[0];   // (B,3,N)
    const float* pose    = (const float*)d_in[1];   // (B,72)
    const float* weights = (const float*)d_in[2];   // (B,24,N)
    float* out = (float*)d_out;                     // (B,3,N)

    const int B = in_sizes[1] / 72;
    const int N = in_sizes[0] / (3 * B);

    const int G = N >> 2;
    int gx = (G + 255) / 256;
    if (gx > 37) gx = 37;           // 37 * 16 = 592 blocks = 4 per SM, single wave
    if (gx < 1) gx = 1;

    dim3 block(256);
    dim3 grid(gx, B);
    skin_kernel<<<grid, block>>>(normals, pose, weights, out, N);
}

// round 5
// speedup vs baseline: 4.9931x; 4.9931x over previous
#include <cuda_runtime.h>

#define NJ 24

// Ancestor chains (root -> joint) for the fixed SMPL tree.
__device__ const int d_chain[NJ][9] = {
    {0,0,0,0,0,0,0,0,0},
    {0,1,0,0,0,0,0,0,0},
    {0,2,0,0,0,0,0,0,0},
    {0,3,0,0,0,0,0,0,0},
    {0,1,4,0,0,0,0,0,0},
    {0,2,5,0,0,0,0,0,0},
    {0,3,6,0,0,0,0,0,0},
    {0,1,4,7,0,0,0,0,0},
    {0,2,5,8,0,0,0,0,0},
    {0,3,6,9,0,0,0,0,0},
    {0,1,4,7,10,0,0,0,0},
    {0,2,5,8,11,0,0,0,0},
    {0,3,6,9,12,0,0,0,0},
    {0,3,6,9,13,0,0,0,0},
    {0,3,6,9,14,0,0,0,0},
    {0,3,6,9,12,15,0,0,0},
    {0,3,6,9,13,16,0,0,0},
    {0,3,6,9,14,17,0,0,0},
    {0,3,6,9,13,16,18,0,0},
    {0,3,6,9,14,17,19,0,0},
    {0,3,6,9,13,16,18,20,0},
    {0,3,6,9,14,17,19,21,0},
    {0,3,6,9,13,16,18,20,22},
    {0,3,6,9,14,17,19,21,23},
};
__device__ const int d_chlen[NJ] = {1,2,2,2,3,3,3,4,4,4,5,5,5,5,5,6,6,6,7,7,8,8,9,9};

typedef unsigned long long u64;

__device__ __forceinline__ u64 fma2(u64 a, u64 b, u64 c) {
    u64 d;
    asm("fma.rn.f32x2 %0, %1, %2, %3;" : "=l"(d) : "l"(a), "l"(b), "l"(c));
    return d;
}
__device__ __forceinline__ u64 mul2(u64 a, u64 b) {
    u64 d;
    asm("mul.rn.f32x2 %0, %1, %2;" : "=l"(d) : "l"(a), "l"(b));
    return d;
}
__device__ __forceinline__ u64 pack_dup(float f) {
    unsigned int u = __float_as_uint(f);
    return ((u64)u << 32) | (u64)u;
}
__device__ __forceinline__ u64 pack2f(float lo, float hi) {
    u64 d;
    asm("mov.b64 %0, {%1, %2};" : "=l"(d) : "r"(__float_as_uint(lo)), "r"(__float_as_uint(hi)));
    return d;
}
__device__ __forceinline__ void unpack2f(u64 v, float& lo, float& hi) {
    unsigned int l, h;
    asm("mov.b64 {%0, %1}, %2;" : "=r"(l), "=r"(h) : "l"(v));
    lo = __uint_as_float(l);
    hi = __uint_as_float(h);
}

__global__ void skin_kernel(const float* __restrict__ normals,
                            const float* __restrict__ pose,
                            const float* __restrict__ W,
                            float* __restrict__ out,
                            int N)
{
    __shared__ float sLoc[NJ][9];   // local per-joint rotations
    __shared__ u64   sRp[NJ][9];    // composed rotations, duplicated as f32x2
    __shared__ float sRs[NJ][9];    // scalar copy (tail path)

    const int b = blockIdx.y;
    const int tid = threadIdx.x;

    // --- Rodrigues (one thread per joint) ---
    if (tid < NJ) {
        const float x = pose[b * 72 + tid * 3 + 0];
        const float y = pose[b * 72 + tid * 3 + 1];
        const float z = pose[b * 72 + tid * 3 + 2];
        const float e = 1e-8f;
        const float a = sqrtf((x + e) * (x + e) + (y + e) * (y + e) + (z + e) * (z + e));
        const float inv = 1.0f / a;
        const float ux = x * inv, uy = y * inv, uz = z * inv;
        float s, c;
        sincosf(a, &s, &c);
        const float C = 1.0f - c;
        sLoc[tid][0] = c + C * ux * ux;
        sLoc[tid][1] = C * ux * uy - s * uz;
        sLoc[tid][2] = C * ux * uz + s * uy;
        sLoc[tid][3] = C * uy * ux + s * uz;
        sLoc[tid][4] = c + C * uy * uy;
        sLoc[tid][5] = C * uy * uz - s * ux;
        sLoc[tid][6] = C * uz * ux - s * uy;
        sLoc[tid][7] = C * uz * uy + s * ux;
        sLoc[tid][8] = c + C * uz * uz;
    }
    __syncthreads();

    // --- parallel chain composition: each joint-thread walks its own ancestor path ---
    if (tid < NJ) {
        float R[9];
        #pragma unroll
        for (int e2 = 0; e2 < 9; e2++) R[e2] = sLoc[0][e2];
        const int len = d_chlen[tid];
        for (int i = 1; i < len; i++) {
            const int j = d_chain[tid][i];
            float T[9];
            #pragma unroll
            for (int r = 0; r < 3; r++)
                #pragma unroll
                for (int cc = 0; cc < 3; cc++)
                    T[r * 3 + cc] = R[r * 3 + 0] * sLoc[j][0 * 3 + cc]
                                  + R[r * 3 + 1] * sLoc[j][1 * 3 + cc]
                                  + R[r * 3 + 2] * sLoc[j][2 * 3 + cc];
            #pragma unroll
            for (int e2 = 0; e2 < 9; e2++) R[e2] = T[e2];
        }
        #pragma unroll
        for (int e2 = 0; e2 < 9; e2++) {
            sRs[tid][e2] = R[e2];
            sRp[tid][e2] = pack_dup(R[e2]);
        }
    }
    __syncthreads();

    const float* Nb = normals + (size_t)b * 3 * N;
    const float* Wb = W + (size_t)b * NJ * N;
    float* Ob = out + (size_t)b * 3 * N;

    const int G = N >> 2;   // full groups of 4 points
    const int g = blockIdx.x * blockDim.x + tid;

    if (g < G) {
        const int n = g << 2;

        const float4 nxv = *reinterpret_cast<const float4*>(Nb + n);
        const float4 nyv = *reinterpret_cast<const float4*>(Nb + (size_t)N + n);
        const float4 nzv = *reinterpret_cast<const float4*>(Nb + 2 * (size_t)N + n);

        const u64 nx0 = pack2f(nxv.x, nxv.y), nx1 = pack2f(nxv.z, nxv.w);
        const u64 ny0 = pack2f(nyv.x, nyv.y), ny1 = pack2f(nyv.z, nyv.w);
        const u64 nz0 = pack2f(nzv.x, nzv.y), nz1 = pack2f(nzv.z, nzv.w);

        u64 a00 = 0, a01 = 0, a10 = 0, a11 = 0, a20 = 0, a21 = 0;

        #pragma unroll
        for (int k = 0; k < NJ; k++) {
            const float4 wv = *reinterpret_cast<const float4*>(Wb + (size_t)k * N + n);
            const u64 w0 = pack2f(wv.x, wv.y);
            const u64 w1 = pack2f(wv.z, wv.w);

            // row 0
            {
                const u64 r0 = sRp[k][0], r1 = sRp[k][1], r2 = sRp[k][2];
                u64 v0 = mul2(r0, nx0); v0 = fma2(r1, ny0, v0); v0 = fma2(r2, nz0, v0);
                a00 = fma2(w0, v0, a00);
                u64 v1 = mul2(r0, nx1); v1 = fma2(r1, ny1, v1); v1 = fma2(r2, nz1, v1);
                a01 = fma2(w1, v1, a01);
            }
            // row 1
            {
                const u64 r3 = sRp[k][3], r4 = sRp[k][4], r5 = sRp[k][5];
                u64 v0 = mul2(r3, nx0); v0 = fma2(r4, ny0, v0); v0 = fma2(r5, nz0, v0);
                a10 = fma2(w0, v0, a10);
                u64 v1 = mul2(r3, nx1); v1 = fma2(r4, ny1, v1); v1 = fma2(r5, nz1, v1);
                a11 = fma2(w1, v1, a11);
            }
            // row 2
            {
                const u64 r6 = sRp[k][6], r7 = sRp[k][7], r8 = sRp[k][8];
                u64 v0 = mul2(r6, nx0); v0 = fma2(r7, ny0, v0); v0 = fma2(r8, nz0, v0);
                a20 = fma2(w0, v0, a20);
                u64 v1 = mul2(r6, nx1); v1 = fma2(r7, ny1, v1); v1 = fma2(r8, nz1, v1);
                a21 = fma2(w1, v1, a21);
            }
        }

        float4 o;
        unpack2f(a00, o.x, o.y); unpack2f(a01, o.z, o.w);
        *reinterpret_cast<float4*>(Ob + n) = o;
        unpack2f(a10, o.x, o.y); unpack2f(a11, o.z, o.w);
        *reinterpret_cast<float4*>(Ob + (size_t)N + n) = o;
        unpack2f(a20, o.x, o.y); unpack2f(a21, o.z, o.w);
        *reinterpret_cast<float4*>(Ob + 2 * (size_t)N + n) = o;
    }

    // --- scalar tail (N % 4 leftover points) ---
    const int rem = N & 3;
    if (rem && blockIdx.x == 0 && tid < rem) {
        const int n = (G << 2) + tid;
        const float xs = Nb[n], ys = Nb[(size_t)N + n], zs = Nb[2 * (size_t)N + n];
        float o0 = 0.f, o1 = 0.f, o2 = 0.f;
        for (int k = 0; k < NJ; k++) {
            const float wv = Wb[(size_t)k * N + n];
            o0 = fmaf(wv, sRs[k][0] * xs + sRs[k][1] * ys + sRs[k][2] * zs, o0);
            o1 = fmaf(wv, sRs[k][3] * xs + sRs[k][4] * ys + sRs[k][5] * zs, o1);
            o2 = fmaf(wv, sRs[k][6] * xs + sRs[k][7] * ys + sRs[k][8] * zs, o2);
        }
        Ob[n] = o0;
        Ob[(size_t)N + n] = o1;
        Ob[2 * (size_t)N + n] = o2;
    }
}

extern "C" void kernel_launch(void* const* d_in, const int* in_sizes, int n_in,
                              void* d_out, int out_size)
{
    const float* normals = (const float*)d_in[0];   // (B,3,N)
    const float* pose    = (const float*)d_in[1];   // (B,72)
    const float* weights = (const float*)d_in[2];   // (B,24,N)
    float* out = (float*)d_out;                     // (B,3,N)

    const int B = in_sizes[1] / 72;
    const int N = in_sizes[0] / (3 * B);

    const int G = N >> 2;
    int gx = (G + 255) / 256;
    if (gx < 1) gx = 1;

    dim3 block(256);
    dim3 grid(gx, B);
    skin_kernel<<<grid, block>>>(normals, pose, weights, out, N);
}